// round 16
// baseline (speedup 1.0000x reference)
#include <cuda_runtime.h>
#include <cuda_bf16.h>
#include <math.h>

// Problem constants
#define BB   2
#define SQ   1024
#define DIM  512
#define NH   8
#define DKH  64
#define NL   6
#define DFF  2048
#define NV   32000
#define MAXS 1025   // MAXSEQ+1

typedef unsigned int u32;
typedef __nv_bfloat16 bf16;

// ---------------- device scratch (no allocations allowed) ----------------
__device__ float g_x   [BB*SQ*DIM];
__device__ bf16  g_h   [BB*SQ*DIM];
__device__ bf16  g_qkvb[3*BB*SQ*DIM];   // q[B,H,S,DK], k[B,H,S,DK], vT[B,H,DK,S]
__device__ float g_rb  [BB*NH*SQ];
__device__ bf16  g_at  [BB*SQ*DIM];
__device__ bf16  g_ff  [BB*SQ*DFF];
__device__ float g_fo  [16*8*2*128*64]; // split-KV O partials (8 MB)
__device__ float g_fml [16*8*2*256];    // split-KV m/l per row
__device__ bf16  g_wb  [35258368];      // all weights as bf16

#define OFF_WQ 0
#define OFF_WK 1572864
#define OFF_WV 3145728
#define OFF_WO 4718592
#define OFF_W1 6291456
#define OFF_W2 12582912
#define OFF_WG 18874368

// ======================= PTX helpers =======================
__device__ __forceinline__ u32 sm32(const void* p) {
    u32 a;
    asm("{ .reg .u64 t; cvta.to.shared.u64 t, %1; cvt.u32.u64 %0, t; }" : "=r"(a) : "l"(p));
    return a;
}
__device__ __forceinline__ void cp_async16(u32 s, const void* g) {
    asm volatile("cp.async.cg.shared.global [%0], [%1], 16;" :: "r"(s), "l"(g));
}
#define CP_COMMIT()  asm volatile("cp.async.commit_group;" ::: "memory")
#define CP_WAIT(N)   asm volatile("cp.async.wait_group " #N ";" ::: "memory")

#define LDSM4(r, addr) \
    asm volatile("ldmatrix.sync.aligned.m8n8.x4.shared.b16 {%0,%1,%2,%3}, [%4];" \
        : "=r"((r)[0]), "=r"((r)[1]), "=r"((r)[2]), "=r"((r)[3]) : "r"(addr))

__device__ __forceinline__ void mma16816(float* c, const u32* a, u32 b0, u32 b1) {
    asm volatile(
        "mma.sync.aligned.m16n8k16.row.col.f32.bf16.bf16.f32 "
        "{%0,%1,%2,%3},{%4,%5,%6,%7},{%8,%9},{%0,%1,%2,%3};"
        : "+f"(c[0]), "+f"(c[1]), "+f"(c[2]), "+f"(c[3])
        : "r"(a[0]), "r"(a[1]), "r"(a[2]), "r"(a[3]), "r"(b0), "r"(b1));
}
__device__ __forceinline__ u32 pack_bf(float lo, float hi) {
    __nv_bfloat162 t = __floats2bfloat162_rn(lo, hi);
    return *(u32*)&t;
}

struct GP {
    const bf16* A; const bf16* B; const bf16* B1; const bf16* B2;
    const float* bias; const float* bias1; const float* bias2;
    const float* resid;
    float* C; bf16* Cb;
    int N, K;
};
enum { M_PLAIN = 0, M_QKV, M_RESID, M_RELU };

// ======================= bf16 NT GEMM, 256 thr, BM=128, BN=128, 3-stage =======================
#define GSMEM(BN) (3 * (16384 + (BN) * 128))

template<int MODE, int BN>
__global__ __launch_bounds__(256, 2) void bmma_k(GP p) {
    constexpr int WN     = BN / 2;
    constexpr int NTN    = WN / 8;
    constexpr int NB16   = WN / 16;
    constexpr int ABYTES = 128 * 128;
    constexpr int BBYTES = BN * 128;
    constexpr int STG    = ABYTES + BBYTES;

    extern __shared__ char sm[];
    const u32 sb = sm32(sm);
    const int t = threadIdx.x, lane = t & 31, warp = t >> 5;
    const int wm = warp >> 1, wn = warp & 1;
    const int n0 = blockIdx.x * BN, m0 = blockIdx.y * 128;

    const bf16* A = p.A;
    const bf16* B = p.B;
    const float* bias = p.bias;

    const int ntile = p.K >> 6;

    auto fill = [&](int it) {
        u32 ab = sb + (it % 3) * STG;
        u32 bb = ab + ABYTES;
        int k0 = it << 6;
        const bf16* Ag = A + (long long)m0 * p.K + k0;
        const bf16* Bg = B + (long long)n0 * p.K + k0;
#pragma unroll
        for (int i = 0; i < 4; ++i) {
            int idx = t + i * 256;
            int r = idx >> 3, c = idx & 7;
            cp_async16(ab + r * 128 + ((c ^ (r & 7)) << 4), Ag + (long long)r * p.K + c * 8);
        }
#pragma unroll
        for (int i = 0; i < BN / 32; ++i) {
            int idx = t + i * 256;
            int r = idx >> 3, c = idx & 7;
            cp_async16(bb + r * 128 + ((c ^ (r & 7)) << 4), Bg + (long long)r * p.K + c * 8);
        }
        CP_COMMIT();
    };

    float acc[2][NTN][4];
#pragma unroll
    for (int i = 0; i < 2; ++i)
#pragma unroll
        for (int j = 0; j < NTN; ++j)
#pragma unroll
            for (int c = 0; c < 4; ++c) acc[i][j][c] = 0.f;

    fill(0);
    if (1 < ntile) fill(1);

    for (int it = 0; it < ntile; ++it) {
        if (it + 1 < ntile) { CP_WAIT(1); } else { CP_WAIT(0); }
        __syncthreads();
        if (it + 2 < ntile) fill(it + 2);

        u32 ab = sb + (it % 3) * STG;
        u32 bb = ab + ABYTES;
#pragma unroll
        for (int ks = 0; ks < 4; ++ks) {
            const int cc = ks * 2 + (lane >> 4);
            u32 a[2][4];
#pragma unroll
            for (int mt = 0; mt < 2; ++mt) {
                int mr = wm * 32 + mt * 16 + (lane & 7) + ((lane >> 3) & 1) * 8;
                LDSM4(a[mt], ab + mr * 128 + ((cc ^ (mr & 7)) << 4));
            }
#pragma unroll
            for (int nb = 0; nb < NB16; ++nb) {
                int nr = wn * WN + nb * 16 + (lane & 7) + ((lane >> 3) & 1) * 8;
                u32 b[4];
                LDSM4(b, bb + nr * 128 + ((cc ^ (nr & 7)) << 4));
#pragma unroll
                for (int mt = 0; mt < 2; ++mt) {
                    mma16816(acc[mt][2 * nb + 0], a[mt], b[0], b[2]);
                    mma16816(acc[mt][2 * nb + 1], a[mt], b[1], b[3]);
                }
            }
        }
    }

#pragma unroll
    for (int mt = 0; mt < 2; ++mt) {
#pragma unroll
        for (int nt = 0; nt < NTN; ++nt) {
            const int n  = n0 + wn * WN + nt * 8 + 2 * (lane & 3);
            const int mlo = m0 + wm * 32 + mt * 16 + (lane >> 2);
            float v0 = acc[mt][nt][0], v1 = acc[mt][nt][1];
            float v2 = acc[mt][nt][2], v3 = acc[mt][nt][3];
            float b0 = bias[n], b1 = bias[n + 1];
            if (MODE == M_PLAIN) {
                *(float2*)(p.C + (long long)mlo * p.N + n)       = make_float2(v0 + b0, v1 + b1);
                *(float2*)(p.C + (long long)(mlo + 8) * p.N + n) = make_float2(v2 + b0, v3 + b1);
            } else if (MODE == M_RELU) {
                float o0 = v0 + b0, o1 = v1 + b1, o2 = v2 + b0, o3 = v3 + b1;
                o0 = o0 > 0.f ? o0 : 0.f; o1 = o1 > 0.f ? o1 : 0.f;
                o2 = o2 > 0.f ? o2 : 0.f; o3 = o3 > 0.f ? o3 : 0.f;
                *(__nv_bfloat162*)(p.Cb + (long long)mlo * p.N + n)       = __floats2bfloat162_rn(o0, o1);
                *(__nv_bfloat162*)(p.Cb + (long long)(mlo + 8) * p.N + n) = __floats2bfloat162_rn(o2, o3);
            }
        }
    }
}

// ======================= small GEMM: BM=64, BN=64, 128 threads, 4 CTAs/SM =======================
#define SSMEM 49152

template<int MODE>
__global__ __launch_bounds__(128, 4) void small_k(GP p) {
    constexpr int ABYTES = 64 * 128;
    constexpr int STG    = 2 * ABYTES;

    extern __shared__ char sm[];
    const u32 sb = sm32(sm);
    const int t = threadIdx.x, lane = t & 31, warp = t >> 5;
    const int wm = warp >> 1, wn = warp & 1;
    const int n0 = blockIdx.x * 64, m0 = blockIdx.y * 64, z = blockIdx.z;

    const bf16* A = p.A;
    const bf16* B; const float* bias;
    if (MODE == M_QKV) {
        B    = (z == 0) ? p.B : (z == 1 ? p.B1 : p.B2);
        bias = (z == 0) ? p.bias : (z == 1 ? p.bias1 : p.bias2);
    } else { B = p.B; bias = p.bias; }

    const int ntile = p.K >> 6;

    auto fill = [&](int it) {
        u32 ab = sb + (it % 3) * STG;
        u32 bb = ab + ABYTES;
        int k0 = it << 6;
        const bf16* Ag = A + (long long)m0 * p.K + k0;
        const bf16* Bg = B + (long long)n0 * p.K + k0;
#pragma unroll
        for (int i = 0; i < 4; ++i) {
            int idx = t + i * 128;
            int r = idx >> 3, c = idx & 7;
            cp_async16(ab + r * 128 + ((c ^ (r & 7)) << 4), Ag + (long long)r * p.K + c * 8);
        }
#pragma unroll
        for (int i = 0; i < 4; ++i) {
            int idx = t + i * 128;
            int r = idx >> 3, c = idx & 7;
            cp_async16(bb + r * 128 + ((c ^ (r & 7)) << 4), Bg + (long long)r * p.K + c * 8);
        }
        CP_COMMIT();
    };

    float acc[2][4][4];
#pragma unroll
    for (int i = 0; i < 2; ++i)
#pragma unroll
        for (int j = 0; j < 4; ++j)
#pragma unroll
            for (int c = 0; c < 4; ++c) acc[i][j][c] = 0.f;

    fill(0);
    if (1 < ntile) fill(1);

    for (int it = 0; it < ntile; ++it) {
        if (it + 1 < ntile) { CP_WAIT(1); } else { CP_WAIT(0); }
        __syncthreads();
        if (it + 2 < ntile) fill(it + 2);

        u32 ab = sb + (it % 3) * STG;
        u32 bb = ab + ABYTES;
#pragma unroll
        for (int ks = 0; ks < 4; ++ks) {
            const int cc = ks * 2 + (lane >> 4);
            u32 a[2][4];
#pragma unroll
            for (int mt = 0; mt < 2; ++mt) {
                int mr = wm * 32 + mt * 16 + (lane & 7) + ((lane >> 3) & 1) * 8;
                LDSM4(a[mt], ab + mr * 128 + ((cc ^ (mr & 7)) << 4));
            }
#pragma unroll
            for (int nb = 0; nb < 2; ++nb) {
                int nr = wn * 32 + nb * 16 + (lane & 7) + ((lane >> 3) & 1) * 8;
                u32 b[4];
                LDSM4(b, bb + nr * 128 + ((cc ^ (nr & 7)) << 4));
#pragma unroll
                for (int mt = 0; mt < 2; ++mt) {
                    mma16816(acc[mt][2 * nb + 0], a[mt], b[0], b[2]);
                    mma16816(acc[mt][2 * nb + 1], a[mt], b[1], b[3]);
                }
            }
        }
    }

#pragma unroll
    for (int mt = 0; mt < 2; ++mt) {
#pragma unroll
        for (int nt = 0; nt < 4; ++nt) {
            const int n  = n0 + wn * 32 + nt * 8 + 2 * (lane & 3);
            const int mlo = m0 + wm * 32 + mt * 16 + (lane >> 2);
            float v0 = acc[mt][nt][0], v1 = acc[mt][nt][1];
            float v2 = acc[mt][nt][2], v3 = acc[mt][nt][3];
            float b0 = bias[n], b1 = bias[n + 1];
            if (MODE == M_RESID) {
                long long i0 = (long long)mlo * p.N + n;
                long long i1 = (long long)(mlo + 8) * p.N + n;
                float2 r0 = *(float2*)(p.resid + i0), r1 = *(float2*)(p.resid + i1);
                *(float2*)(p.C + i0) = make_float2(r0.x + v0 + b0, r0.y + v1 + b1);
                *(float2*)(p.C + i1) = make_float2(r1.x + v2 + b0, r1.y + v3 + b1);
            } else if (MODE == M_QKV) {
                float o0 = v0 + b0, o1 = v1 + b1, o2 = v2 + b0, o3 = v3 + b1;
                const long long TSZ = (long long)BB * SQ * DIM;
                int hh = n >> 6, dk = n & 63;
#pragma unroll
                for (int half = 0; half < 2; ++half) {
                    int m = mlo + half * 8;
                    int b = m >> 10, s2 = m & (SQ - 1);
                    float e0 = half ? o2 : o0, e1 = half ? o3 : o1;
                    if (z < 2) {
                        *(__nv_bfloat162*)(p.Cb + z * TSZ + (((long long)(b * NH + hh)) * SQ + s2) * DKH + dk)
                            = __floats2bfloat162_rn(e0, e1);
                    } else {
                        bf16* base = p.Cb + 2 * TSZ + ((long long)(b * NH + hh)) * DKH * SQ + s2;
                        base[(long long)dk * SQ]       = __float2bfloat16_rn(e0);
                        base[(long long)(dk + 1) * SQ] = __float2bfloat16_rn(e1);
                    }
                }
            }
        }
    }
}

// ======================= split-KV fused flash attention =======================
// 12 work units per (b,h): qb 0..3 single; qb 4..7 split into two KV halves.
// Split units emit unnormalized O + (m,l) partials; combine_k merges.
#define FA_QBYTES  16384
#define FA_KBYTES  16384
#define FA_VBYTES  16384
#define FA_STG     (FA_KBYTES + FA_VBYTES + 512)
#define FA_SMEM    (FA_QBYTES + 2 * FA_STG)

__global__ __launch_bounds__(256) void flash_k(const bf16* __restrict__ qg,
                                               const bf16* __restrict__ kg,
                                               const bf16* __restrict__ vg,
                                               const float* __restrict__ rbias,
                                               bf16* __restrict__ at,
                                               float* __restrict__ fo,
                                               float* __restrict__ fml) {
    extern __shared__ char sm[];
    const u32 sb = sm32(sm);
    const int t = threadIdx.x, lane = t & 31, warp = t >> 5;
    // heavy-first unit table: (qb, kv_start, kv_end)
    const int qb_t[12] = {7, 7, 6, 3, 6, 5, 5, 4, 2, 4, 1, 0};
    const int ks_t[12] = {0, 4, 0, 0, 4, 0, 3, 0, 0, 3, 0, 0};
    const int ke_t[12] = {4, 8, 4, 4, 7, 3, 6, 3, 3, 5, 2, 1};
    const int u = blockIdx.x, z = blockIdx.y;
    const int qb = qb_t[u], kvs = ks_t[u], kve = ke_t[u];
    const bool split = (qb >= 4);
    const int part = (kvs != 0) ? 1 : 0;
    const int b = z >> 3, h = z & 7;

    const bf16* Qg = qg + ((long long)z * SQ + qb * 128) * DKH;
    const bf16* Kg = kg + (long long)z * SQ * DKH;
    const bf16* Vg = vg + (long long)z * DKH * SQ;
    const float* rbg = rbias + (long long)z * SQ;

#pragma unroll
    for (int i = 0; i < 4; ++i) {
        int idx = t + i * 256;
        int r = idx >> 3, c = idx & 7;
        cp_async16(sb + r * 128 + ((c ^ (r & 7)) << 4), Qg + (long long)r * DKH + c * 8);
    }
    auto fillKV = [&](int kb) {
        u32 kbse = sb + FA_QBYTES + (kb & 1) * FA_STG;
        u32 vbse = kbse + FA_KBYTES;
        u32 rbse = vbse + FA_VBYTES;
        const bf16* Kt = Kg + (long long)kb * 128 * DKH;
        const bf16* Vt = Vg + kb * 128;
#pragma unroll
        for (int i = 0; i < 4; ++i) {
            int idx = t + i * 256;
            int r = idx >> 3, c = idx & 7;
            cp_async16(kbse + r * 128 + ((c ^ (r & 7)) << 4), Kt + (long long)r * DKH + c * 8);
        }
#pragma unroll
        for (int i = 0; i < 4; ++i) {
            int idx = t + i * 256;
            int r = idx >> 4, c = idx & 15;
            cp_async16(vbse + r * 256 + ((c ^ (r & 7)) << 4), Vt + (long long)r * SQ + c * 8);
        }
        if (t < 32) cp_async16(rbse + t * 16, rbg + kb * 128 + t * 4);
        CP_COMMIT();
    };
    fillKV(kvs);

    float o[8][4];
#pragma unroll
    for (int i = 0; i < 8; ++i)
#pragma unroll
        for (int c = 0; c < 4; ++c) o[i][c] = 0.f;
    float m0 = -1e30f, m1 = -1e30f, l0 = 0.f, l1 = 0.f;

    u32 aq[4][4];
    bool qloaded = false;

    for (int kb = kvs; kb < kve; ++kb) {
        CP_WAIT(0);
        __syncthreads();
        if (kb + 1 < kve) fillKV(kb + 1);

        if (!qloaded) {
#pragma unroll
            for (int ks = 0; ks < 4; ++ks) {
                int mr = warp * 16 + (lane & 7) + ((lane >> 3) & 1) * 8;
                int cc = ks * 2 + (lane >> 4);
                LDSM4(aq[ks], sb + mr * 128 + ((cc ^ (mr & 7)) << 4));
            }
            qloaded = true;
        }

        u32 kbse = sb + FA_QBYTES + (kb & 1) * FA_STG;
        u32 vbse = kbse + FA_KBYTES;
        float* rbs = (float*)(sm + (kbse - sb) + FA_KBYTES + FA_VBYTES);

        float s[16][4];
#pragma unroll
        for (int i = 0; i < 16; ++i)
#pragma unroll
            for (int c = 0; c < 4; ++c) s[i][c] = 0.f;
#pragma unroll
        for (int ks = 0; ks < 4; ++ks) {
            const int cc = ks * 2 + (lane >> 4);
#pragma unroll
            for (int np = 0; np < 8; ++np) {
                int nr = np * 16 + (lane & 7) + ((lane >> 3) & 1) * 8;
                u32 bfr[4];
                LDSM4(bfr, kbse + nr * 128 + ((cc ^ (nr & 7)) << 4));
                mma16816(s[2 * np + 0], aq[ks], bfr[0], bfr[2]);
                mma16816(s[2 * np + 1], aq[ks], bfr[1], bfr[3]);
            }
        }

        const int colq = 2 * (lane & 3);
        const int r0 = warp * 16 + (lane >> 2), r1 = r0 + 8;
#pragma unroll
        for (int nt = 0; nt < 16; ++nt) {
            float2 rb2 = *(float2*)(rbs + nt * 8 + colq);
            s[nt][0] = s[nt][0] * 0.125f + rb2.x;
            s[nt][1] = s[nt][1] * 0.125f + rb2.y;
            s[nt][2] = s[nt][2] * 0.125f + rb2.x;
            s[nt][3] = s[nt][3] * 0.125f + rb2.y;
        }
        if (kb == qb) {     // diagonal block (global mask: key > row)
#pragma unroll
            for (int nt = 0; nt < 16; ++nt) {
                int c0 = nt * 8 + colq;
                if (c0 > r0)     s[nt][0] = -1e30f;
                if (c0 + 1 > r0) s[nt][1] = -1e30f;
                if (c0 > r1)     s[nt][2] = -1e30f;
                if (c0 + 1 > r1) s[nt][3] = -1e30f;
            }
        }

        float mx0 = -1e30f, mx1 = -1e30f;
#pragma unroll
        for (int nt = 0; nt < 16; ++nt) {
            mx0 = fmaxf(mx0, fmaxf(s[nt][0], s[nt][1]));
            mx1 = fmaxf(mx1, fmaxf(s[nt][2], s[nt][3]));
        }
        mx0 = fmaxf(mx0, __shfl_xor_sync(0xffffffffu, mx0, 1));
        mx0 = fmaxf(mx0, __shfl_xor_sync(0xffffffffu, mx0, 2));
        mx1 = fmaxf(mx1, __shfl_xor_sync(0xffffffffu, mx1, 1));
        mx1 = fmaxf(mx1, __shfl_xor_sync(0xffffffffu, mx1, 2));
        float M0 = fmaxf(m0, mx0), M1 = fmaxf(m1, mx1);
        float a0 = expf(m0 - M0), a1 = expf(m1 - M1);
        float sum0 = 0.f, sum1 = 0.f;
#pragma unroll
        for (int nt = 0; nt < 16; ++nt) {
            s[nt][0] = expf(s[nt][0] - M0); sum0 += s[nt][0];
            s[nt][1] = expf(s[nt][1] - M0); sum0 += s[nt][1];
            s[nt][2] = expf(s[nt][2] - M1); sum1 += s[nt][2];
            s[nt][3] = expf(s[nt][3] - M1); sum1 += s[nt][3];
        }
        sum0 += __shfl_xor_sync(0xffffffffu, sum0, 1);
        sum0 += __shfl_xor_sync(0xffffffffu, sum0, 2);
        sum1 += __shfl_xor_sync(0xffffffffu, sum1, 1);
        sum1 += __shfl_xor_sync(0xffffffffu, sum1, 2);
        l0 = l0 * a0 + sum0;  l1 = l1 * a1 + sum1;
        m0 = M0;  m1 = M1;
#pragma unroll
        for (int i = 0; i < 8; ++i) {
            o[i][0] *= a0; o[i][1] *= a0; o[i][2] *= a1; o[i][3] *= a1;
        }

#pragma unroll
        for (int kv = 0; kv < 8; ++kv) {
            u32 pa[4];
            pa[0] = pack_bf(s[2 * kv][0],     s[2 * kv][1]);
            pa[1] = pack_bf(s[2 * kv][2],     s[2 * kv][3]);
            pa[2] = pack_bf(s[2 * kv + 1][0], s[2 * kv + 1][1]);
            pa[3] = pack_bf(s[2 * kv + 1][2], s[2 * kv + 1][3]);
            const int cc = kv * 2 + (lane >> 4);
#pragma unroll
            for (int nd = 0; nd < 4; ++nd) {
                int nr = nd * 16 + (lane & 7) + ((lane >> 3) & 1) * 8;
                u32 bfr[4];
                LDSM4(bfr, vbse + nr * 256 + ((cc ^ (nr & 7)) << 4));
                mma16816(o[2 * nd + 0], pa, bfr[0], bfr[2]);
                mma16816(o[2 * nd + 1], pa, bfr[1], bfr[3]);
            }
        }
        __syncthreads();
    }

    const int lr0 = warp * 16 + (lane >> 2);
    if (!split) {
        float inv0 = 1.f / l0, inv1 = 1.f / l1;
        const int gr = qb * 128 + lr0;
#pragma unroll
        for (int nd = 0; nd < 8; ++nd) {
            int n = h * DKH + nd * 8 + 2 * (lane & 3);
            __nv_bfloat162 v0 = __floats2bfloat162_rn(o[nd][0] * inv0, o[nd][1] * inv0);
            __nv_bfloat162 v1 = __floats2bfloat162_rn(o[nd][2] * inv1, o[nd][3] * inv1);
            *(__nv_bfloat162*)(at + ((long long)(b * SQ) + gr) * DIM + n)     = v0;
            *(__nv_bfloat162*)(at + ((long long)(b * SQ) + gr + 8) * DIM + n) = v1;
        }
    } else {
        const int pidx = ((z * 8 + qb) * 2 + part);
        float* Op = fo + (long long)pidx * 8192;
#pragma unroll
        for (int nd = 0; nd < 8; ++nd) {
            int n = nd * 8 + 2 * (lane & 3);
            *(float2*)(Op + (long long)lr0 * 64 + n)       = make_float2(o[nd][0], o[nd][1]);
            *(float2*)(Op + (long long)(lr0 + 8) * 64 + n) = make_float2(o[nd][2], o[nd][3]);
        }
        if ((lane & 3) == 0) {
            fml[pidx * 256 + lr0]           = m0;
            fml[pidx * 256 + 128 + lr0]     = l0;
            fml[pidx * 256 + lr0 + 8]       = m1;
            fml[pidx * 256 + 128 + lr0 + 8] = l1;
        }
    }
}

// combine split-KV partials: qb 4..7
__global__ __launch_bounds__(256) void combine_k(const float* __restrict__ fo,
                                                 const float* __restrict__ fml,
                                                 bf16* __restrict__ at) {
    const int qb = 4 + blockIdx.x, z = blockIdx.y;
    const int b = z >> 3, h = z & 7;
    const int p0 = (z * 8 + qb) * 2, p1 = p0 + 1;
    const int t = threadIdx.x;
    const int r = t >> 1, half = t & 1;
    float m0 = fml[p0 * 256 + r], l0 = fml[p0 * 256 + 128 + r];
    float m1 = fml[p1 * 256 + r], l1 = fml[p1 * 256 + 128 + r];
    float M = fmaxf(m0, m1);
    float a0 = expf(m0 - M), a1 = expf(m1 - M);
    float inv = 1.f / (a0 * l0 + a1 * l1);
    a0 *= inv; a1 *= inv;
    const float* s0 = fo + (long long)p0 * 8192 + r * 64 + half * 32;
    const float* s1 = fo + (long long)p1 * 8192 + r * 64 + half * 32;
    bf16* dst = at + ((long long)(b * SQ) + qb * 128 + r) * DIM + h * DKH + half * 32;
#pragma unroll
    for (int c = 0; c < 32; c += 8) {
        float4 u0 = *(const float4*)(s0 + c),     w0 = *(const float4*)(s1 + c);
        float4 u1 = *(const float4*)(s0 + c + 4), w1 = *(const float4*)(s1 + c + 4);
        __nv_bfloat162 o0 = __floats2bfloat162_rn(a0 * u0.x + a1 * w0.x, a0 * u0.y + a1 * w0.y);
        __nv_bfloat162 o1 = __floats2bfloat162_rn(a0 * u0.z + a1 * w0.z, a0 * u0.w + a1 * w0.w);
        __nv_bfloat162 o2 = __floats2bfloat162_rn(a0 * u1.x + a1 * w1.x, a0 * u1.y + a1 * w1.y);
        __nv_bfloat162 o3 = __floats2bfloat162_rn(a0 * u1.z + a1 * w1.z, a0 * u1.w + a1 * w1.w);
        *(__nv_bfloat162*)(dst + c)     = o0;
        *(__nv_bfloat162*)(dst + c + 2) = o1;
        *(__nv_bfloat162*)(dst + c + 4) = o2;
        *(__nv_bfloat162*)(dst + c + 6) = o3;
    }
}

// ---------------- merged weight f32 -> bf16 conversion ----------------
struct CvtAll { const float* s[7]; bf16* d[7]; int cum[8]; };
__global__ __launch_bounds__(256) void cvtall_k(CvtAll j) {
    int g = blockIdx.x * 256 + threadIdx.x;
    if (g >= j.cum[7]) return;
    int seg = 0;
#pragma unroll
    for (int i = 1; i < 7; ++i) seg += (g >= j.cum[i]);
    int local = g - j.cum[seg];
    float4 v = ((const float4*)j.s[seg])[local];
    __nv_bfloat162* d2 = (__nv_bfloat162*)j.d[seg] + (long long)local * 2;
    d2[0] = __floats2bfloat162_rn(v.x, v.y);
    d2[1] = __floats2bfloat162_rn(v.z, v.w);
}

// ---------------- shared LN math (shuffle reductions) ----------------
__device__ __forceinline__ void ln_write(float v0, float v1, const float* ga,
                                         const float* be, bf16* yr, int t,
                                         float* wred) {
    int lane = t & 31, w = t >> 5;
    float s = v0 + v1;
#pragma unroll
    for (int o = 16; o > 0; o >>= 1) s += __shfl_xor_sync(0xffffffffu, s, o);
    if (lane == 0) wred[w] = s;
    __syncthreads();
    if (w == 0) {
        float a = (lane < 8) ? wred[lane] : 0.f;
#pragma unroll
        for (int o = 4; o > 0; o >>= 1) a += __shfl_xor_sync(0xffffffffu, a, o);
        if (lane == 0) wred[8] = a;
    }
    __syncthreads();
    float mean = wred[8] * (1.f / (float)DIM);
    float d0 = v0 - mean, d1 = v1 - mean;
    float q = d0 * d0 + d1 * d1;
#pragma unroll
    for (int o = 16; o > 0; o >>= 1) q += __shfl_xor_sync(0xffffffffu, q, o);
    if (lane == 0) wred[w] = q;
    __syncthreads();
    if (w == 0) {
        float a = (lane < 8) ? wred[lane] : 0.f;
#pragma unroll
        for (int o = 4; o > 0; o >>= 1) a += __shfl_xor_sync(0xffffffffu, a, o);
        if (lane == 0) wred[8] = a;
    }
    __syncthreads();
    float stdv = sqrtf(wred[8] / (float)(DIM - 1));
    float inv  = 1.f / (stdv + 1e-6f);
    yr[t]       = __float2bfloat16_rn(ga[t] * d0 * inv + be[t]);
    yr[t + 256] = __float2bfloat16_rn(ga[t + 256] * d1 * inv + be[t + 256]);
}

__global__ void ln_k(const float* x, const float* ga, const float* be, bf16* y) {
    __shared__ float wred[9];
    int row = blockIdx.x, t = threadIdx.x;
    const float* xr = x + (long long)row * DIM;
    float v0 = xr[t], v1 = xr[t + 256];
    ln_write(v0, v1, ga, be, y + (long long)row * DIM, t, wred);
}

// ---------------- embedding + PE, fused with layer-0 LN ----------------
__global__ void embed_k(const int* inp, const float* emb,
                        const float* ga, const float* be,
                        float* x, bf16* h) {
    __shared__ float wred[9];
    int row = blockIdx.x, t = threadIdx.x;
    int s   = row & (SQ - 1);
    int tok = inp[row];
    const float* e = emb + (long long)tok * DIM;
    const float ln10k_over_d = 9.210340371976184f / (float)DIM;
    float v[2];
#pragma unroll
    for (int i = 0; i < 2; ++i) {
        int d = t + i * 256;
        int   i2  = d & ~1;
        float dv  = expf(-(float)i2 * ln10k_over_d);
        float arg = (float)s * dv;
        float pe  = (d & 1) ? cosf(arg) : sinf(arg);
        v[i] = e[d] * 22.62741699796952f + pe;
        x[(long long)row * DIM + d] = v[i];
    }
    ln_write(v[0], v[1], ga, be, h + (long long)row * DIM, t, wred);
}

// ---------------- relative bias: r[b,h,k] = scale * dot(q[b,h,k], pe[h,k]) ----
__global__ void relbias_k(const bf16* q, const float* rel, float* r) {
    int idx  = blockIdx.x * 8 + (threadIdx.x >> 5);
    int lane = threadIdx.x & 31;
    int k = idx & (SQ - 1);
    int h = (idx >> 10) & (NH - 1);
    const bf16*  qp = q   + (long long)idx * DKH;
    const float* pp = rel + ((long long)h * MAXS + k) * DKH;
    float d = __bfloat162float(qp[lane]) * pp[lane]
            + __bfloat162float(qp[lane + 32]) * pp[lane + 32];
    for (int o = 16; o > 0; o >>= 1) d += __shfl_xor_sync(0xffffffffu, d, o);
    if (lane == 0) r[idx] = d * 0.125f;
}

// ---------------- log_softmax: smem row cache, 2 DRAM passes ----------------
#define LS_SMEM (NV * 4 + 2048)
__global__ __launch_bounds__(512) void logsoftmax_k(float* out) {
    extern __shared__ float row[];
    float* red = row + NV;
    float* r = out + (long long)blockIdx.x * NV;
    int t = threadIdx.x;
    float mx = -1e30f;
    for (int k = t * 4; k < NV; k += 2048) {
        float4 v = *(const float4*)(r + k);
        *(float4*)(row + k) = v;
        mx = fmaxf(mx, fmaxf(fmaxf(v.x, v.y), fmaxf(v.z, v.w)));
    }
    red[t] = mx; __syncthreads();
    for (int o = 256; o > 0; o >>= 1) { if (t < o) red[t] = fmaxf(red[t], red[t + o]); __syncthreads(); }
    mx = red[0]; __syncthreads();
    float sum = 0.f;
    for (int k = t * 4; k < NV; k += 2048) {
        float4 v = *(const float4*)(row + k);
        sum += expf(v.x - mx) + expf(v.y - mx) + expf(v.z - mx) + expf(v.w - mx);
    }
    red[t] = sum; __syncthreads();
    for (int o = 256; o > 0; o >>= 1) { if (t < o) red[t] += red[t + o]; __syncthreads(); }
    float lse = mx + logf(red[0]);
    for (int k = t * 4; k < NV; k += 2048) {
        float4 v = *(const float4*)(row + k);
        v.x -= lse; v.y -= lse; v.z -= lse; v.w -= lse;
        *(float4*)(r + k) = v;
    }
}

// ---------------- host driver ----------------
static inline GP mkgp(const bf16* A, const bf16* B, const float* bias, int N, int K) {
    GP p; p.A = A; p.B = B; p.B1 = nullptr; p.B2 = nullptr;
    p.bias = bias; p.bias1 = nullptr; p.bias2 = nullptr;
    p.resid = nullptr; p.C = nullptr; p.Cb = nullptr;
    p.N = N; p.K = K;
    return p;
}

extern "C" void kernel_launch(void* const* d_in, const int* in_sizes, int n_in,
                              void* d_out, int out_size) {
    const int*   inp   = (const int*)  d_in[0];
    const float* emb   = (const float*)d_in[2];
    const float* Wq    = (const float*)d_in[3];
    const float* bq    = (const float*)d_in[4];
    const float* Wk    = (const float*)d_in[5];
    const float* bk    = (const float*)d_in[6];
    const float* Wv    = (const float*)d_in[7];
    const float* bv    = (const float*)d_in[8];
    const float* Wo    = (const float*)d_in[9];
    const float* bo    = (const float*)d_in[10];
    const float* rel   = (const float*)d_in[11];
    const float* ln1a  = (const float*)d_in[12];
    const float* ln1b  = (const float*)d_in[13];
    const float* ln2a  = (const float*)d_in[14];
    const float* ln2b  = (const float*)d_in[15];
    const float* W1    = (const float*)d_in[16];
    const float* b1    = (const float*)d_in[17];
    const float* W2    = (const float*)d_in[18];
    const float* b2    = (const float*)d_in[19];
    const float* lnfa  = (const float*)d_in[20];
    const float* lnfb  = (const float*)d_in[21];
    const float* Wg    = (const float*)d_in[22];
    const float* bg    = (const float*)d_in[23];
    float* out = (float*)d_out;

    float *x, *rb, *fo, *fml;
    bf16 *h, *qkvb, *at, *ff, *wb;
    cudaGetSymbolAddress((void**)&x,    g_x);
    cudaGetSymbolAddress((void**)&h,    g_h);
    cudaGetSymbolAddress((void**)&qkvb, g_qkvb);
    cudaGetSymbolAddress((void**)&rb,   g_rb);
    cudaGetSymbolAddress((void**)&at,   g_at);
    cudaGetSymbolAddress((void**)&ff,   g_ff);
    cudaGetSymbolAddress((void**)&fo,   g_fo);
    cudaGetSymbolAddress((void**)&fml,  g_fml);
    cudaGetSymbolAddress((void**)&wb,   g_wb);

    const int Mtok = BB * SQ;                     // 2048
    const long long TSZ = (long long)Mtok * DIM;  // 1,048,576
    bf16* q  = qkvb;
    bf16* k_ = qkvb + TSZ;
    bf16* vt = qkvb + 2 * TSZ;

    cudaFuncSetAttribute(bmma_k<M_PLAIN, 128>, cudaFuncAttributeMaxDynamicSharedMemorySize, GSMEM(128));
    cudaFuncSetAttribute(bmma_k<M_RELU,  128>, cudaFuncAttributeMaxDynamicSharedMemorySize, GSMEM(128));
    cudaFuncSetAttribute(small_k<M_QKV>,   cudaFuncAttributeMaxDynamicSharedMemorySize, SSMEM);
    cudaFuncSetAttribute(small_k<M_RESID>, cudaFuncAttributeMaxDynamicSharedMemorySize, SSMEM);
    cudaFuncSetAttribute(flash_k,      cudaFuncAttributeMaxDynamicSharedMemorySize, FA_SMEM);
    cudaFuncSetAttribute(logsoftmax_k, cudaFuncAttributeMaxDynamicSharedMemorySize, LS_SMEM);

    // ---- all weights -> bf16 in one launch ----
    {
        const int n1 = NL * DIM * DIM / 4;
        const int n2 = NL * DFF * DIM / 4;
        const int ng = NV * DIM / 4;
        CvtAll j;
        j.s[0] = Wq; j.s[1] = Wk; j.s[2] = Wv; j.s[3] = Wo; j.s[4] = W1; j.s[5] = W2; j.s[6] = Wg;
        j.d[0] = wb + OFF_WQ; j.d[1] = wb + OFF_WK; j.d[2] = wb + OFF_WV; j.d[3] = wb + OFF_WO;
        j.d[4] = wb + OFF_W1; j.d[5] = wb + OFF_W2; j.d[6] = wb + OFF_WG;
        j.cum[0] = 0;
        j.cum[1] = n1; j.cum[2] = 2 * n1; j.cum[3] = 3 * n1; j.cum[4] = 4 * n1;
        j.cum[5] = 4 * n1 + n2; j.cum[6] = 4 * n1 + 2 * n2; j.cum[7] = 4 * n1 + 2 * n2 + ng;
        cvtall_k<<<(j.cum[7] + 255) / 256, 256>>>(j);
    }

    // embedding + layer-0 LN fused
    embed_k<<<Mtok, 256>>>(inp, emb, ln1a, ln1b, x, h);

    for (int l = 0; l < NL; ++l) {
        const long long wOff = (long long)l * DIM * DIM;
        const long long fOff = (long long)l * DFF * DIM;

        if (l > 0)
            ln_k<<<Mtok, 256>>>(x, ln1a + l * DIM, ln1b + l * DIM, h);

        // fused QKV (small_k)
        {
            GP p = mkgp(h, wb + OFF_WQ + wOff, bq + l * DIM, DIM, DIM);
            p.B1 = wb + OFF_WK + wOff;  p.B2 = wb + OFF_WV + wOff;
            p.bias1 = bk + l * DIM;     p.bias2 = bv + l * DIM;
            p.Cb = qkvb;
            small_k<M_QKV><<<dim3(DIM / 64, Mtok / 64, 3), 128, SSMEM>>>(p);
        }

        relbias_k<<<BB * NH * SQ / 8, 256>>>(q, rel + (long long)l * NH * MAXS * DKH, rb);

        // split-KV flash attention + combine
        flash_k<<<dim3(12, BB * NH), 256, FA_SMEM>>>(q, k_, vt, rb, at, fo, fml);
        combine_k<<<dim3(4, BB * NH), 256>>>(fo, fml, at);

        // x = x + attn @ Wo^T + bo (small_k)
        {
            GP p = mkgp(at, wb + OFF_WO + wOff, bo + l * DIM, DIM, DIM);
            p.resid = x; p.C = x;
            small_k<M_RESID><<<dim3(DIM / 64, Mtok / 64, 1), 128, SSMEM>>>(p);
        }

        ln_k<<<Mtok, 256>>>(x, ln2a + l * DIM, ln2b + l * DIM, h);

        // ffn = relu(h @ W1^T + b1) -> bf16 (bmma_k BN=128)
        {
            GP p = mkgp(h, wb + OFF_W1 + fOff, b1 + l * DFF, DFF, DIM);
            p.Cb = ff;
            bmma_k<M_RELU, 128><<<dim3(DFF / 128, Mtok / 128, 1), 256, GSMEM(128)>>>(p);
        }
        // x = x + ffn @ W2^T + b2 (small_k)
        {
            GP p = mkgp(ff, wb + OFF_W2 + fOff, b2 + l * DIM, DIM, DFF);
            p.resid = x; p.C = x;
            small_k<M_RESID><<<dim3(DIM / 64, Mtok / 64, 1), 128, SSMEM>>>(p);
        }
    }

    ln_k<<<Mtok, 256>>>(x, lnfa, lnfb, h);

    // logits = h @ Wg^T + bg -> d_out (bmma_k BN=128)
    {
        GP p = mkgp(h, wb + OFF_WG, bg, NV, DIM);
        p.C = out;
        bmma_k<M_PLAIN, 128><<<dim3(NV / 128, Mtok / 128, 1), 256, GSMEM(128)>>>(p);
    }

    logsoftmax_k<<<Mtok, 512, LS_SMEM>>>(out);
}

// round 17
// speedup vs baseline: 1.0800x; 1.0800x over previous
#include <cuda_runtime.h>
#include <cuda_bf16.h>
#include <math.h>

// Problem constants
#define BB   2
#define SQ   1024
#define DIM  512
#define NH   8
#define DKH  64
#define NL   6
#define DFF  2048
#define NV   32000
#define MAXS 1025   // MAXSEQ+1

typedef unsigned int u32;
typedef __nv_bfloat16 bf16;

// ---------------- device scratch (no allocations allowed) ----------------
__device__ float g_x   [BB*SQ*DIM];
__device__ bf16  g_h   [BB*SQ*DIM];
__device__ bf16  g_qkvb[3*BB*SQ*DIM];   // q[B,H,S,DK], k[B,H,S,DK], vT[B,H,DK,S]
__device__ float g_rb  [BB*NH*SQ];
__device__ bf16  g_at  [BB*SQ*DIM];
__device__ bf16  g_ff  [BB*SQ*DFF];
__device__ bf16  g_wb  [35258368];      // all weights as bf16

#define OFF_WQ 0
#define OFF_WK 1572864
#define OFF_WV 3145728
#define OFF_WO 4718592
#define OFF_W1 6291456
#define OFF_W2 12582912
#define OFF_WG 18874368

// ======================= PTX helpers =======================
__device__ __forceinline__ u32 sm32(const void* p) {
    u32 a;
    asm("{ .reg .u64 t; cvta.to.shared.u64 t, %1; cvt.u32.u64 %0, t; }" : "=r"(a) : "l"(p));
    return a;
}
__device__ __forceinline__ void cp_async16(u32 s, const void* g) {
    asm volatile("cp.async.cg.shared.global [%0], [%1], 16;" :: "r"(s), "l"(g));
}
#define CP_COMMIT()  asm volatile("cp.async.commit_group;" ::: "memory")
#define CP_WAIT(N)   asm volatile("cp.async.wait_group " #N ";" ::: "memory")

#define LDSM4(r, addr) \
    asm volatile("ldmatrix.sync.aligned.m8n8.x4.shared.b16 {%0,%1,%2,%3}, [%4];" \
        : "=r"((r)[0]), "=r"((r)[1]), "=r"((r)[2]), "=r"((r)[3]) : "r"(addr))

__device__ __forceinline__ void mma16816(float* c, const u32* a, u32 b0, u32 b1) {
    asm volatile(
        "mma.sync.aligned.m16n8k16.row.col.f32.bf16.bf16.f32 "
        "{%0,%1,%2,%3},{%4,%5,%6,%7},{%8,%9},{%0,%1,%2,%3};"
        : "+f"(c[0]), "+f"(c[1]), "+f"(c[2]), "+f"(c[3])
        : "r"(a[0]), "r"(a[1]), "r"(a[2]), "r"(a[3]), "r"(b0), "r"(b1));
}
__device__ __forceinline__ u32 pack_bf(float lo, float hi) {
    __nv_bfloat162 t = __floats2bfloat162_rn(lo, hi);
    return *(u32*)&t;
}

struct GP {
    const bf16* A; const bf16* B; const bf16* B1; const bf16* B2;
    const float* bias; const float* bias1; const float* bias2;
    const float* resid;
    float* C; bf16* Cb;
    int N, K;
};
enum { M_PLAIN = 0, M_QKV, M_RESID, M_RELU };

// ======================= bf16 NT GEMM, 256 thr, BM=128, BN=128, 3-stage =======================
// (many-wave / big-N GEMMs: W1 and vocab)
#define GSMEM(BN) (3 * (16384 + (BN) * 128))

template<int MODE, int BN>
__global__ __launch_bounds__(256, 2) void bmma_k(GP p) {
    constexpr int WN     = BN / 2;
    constexpr int NTN    = WN / 8;
    constexpr int NB16   = WN / 16;
    constexpr int ABYTES = 128 * 128;
    constexpr int BBYTES = BN * 128;
    constexpr int STG    = ABYTES + BBYTES;

    extern __shared__ char sm[];
    const u32 sb = sm32(sm);
    const int t = threadIdx.x, lane = t & 31, warp = t >> 5;
    const int wm = warp >> 1, wn = warp & 1;
    const int n0 = blockIdx.x * BN, m0 = blockIdx.y * 128;

    const bf16* A = p.A;
    const bf16* B = p.B;
    const float* bias = p.bias;

    const int ntile = p.K >> 6;

    auto fill = [&](int it) {
        u32 ab = sb + (it % 3) * STG;
        u32 bb = ab + ABYTES;
        int k0 = it << 6;
        const bf16* Ag = A + (long long)m0 * p.K + k0;
        const bf16* Bg = B + (long long)n0 * p.K + k0;
#pragma unroll
        for (int i = 0; i < 4; ++i) {
            int idx = t + i * 256;
            int r = idx >> 3, c = idx & 7;
            cp_async16(ab + r * 128 + ((c ^ (r & 7)) << 4), Ag + (long long)r * p.K + c * 8);
        }
#pragma unroll
        for (int i = 0; i < BN / 32; ++i) {
            int idx = t + i * 256;
            int r = idx >> 3, c = idx & 7;
            cp_async16(bb + r * 128 + ((c ^ (r & 7)) << 4), Bg + (long long)r * p.K + c * 8);
        }
        CP_COMMIT();
    };

    float acc[2][NTN][4];
#pragma unroll
    for (int i = 0; i < 2; ++i)
#pragma unroll
        for (int j = 0; j < NTN; ++j)
#pragma unroll
            for (int c = 0; c < 4; ++c) acc[i][j][c] = 0.f;

    fill(0);
    if (1 < ntile) fill(1);

    for (int it = 0; it < ntile; ++it) {
        if (it + 1 < ntile) { CP_WAIT(1); } else { CP_WAIT(0); }
        __syncthreads();
        if (it + 2 < ntile) fill(it + 2);

        u32 ab = sb + (it % 3) * STG;
        u32 bb = ab + ABYTES;
#pragma unroll
        for (int ks = 0; ks < 4; ++ks) {
            const int cc = ks * 2 + (lane >> 4);
            u32 a[2][4];
#pragma unroll
            for (int mt = 0; mt < 2; ++mt) {
                int mr = wm * 32 + mt * 16 + (lane & 7) + ((lane >> 3) & 1) * 8;
                LDSM4(a[mt], ab + mr * 128 + ((cc ^ (mr & 7)) << 4));
            }
#pragma unroll
            for (int nb = 0; nb < NB16; ++nb) {
                int nr = wn * WN + nb * 16 + (lane & 7) + ((lane >> 3) & 1) * 8;
                u32 b[4];
                LDSM4(b, bb + nr * 128 + ((cc ^ (nr & 7)) << 4));
#pragma unroll
                for (int mt = 0; mt < 2; ++mt) {
                    mma16816(acc[mt][2 * nb + 0], a[mt], b[0], b[2]);
                    mma16816(acc[mt][2 * nb + 1], a[mt], b[1], b[3]);
                }
            }
        }
    }

#pragma unroll
    for (int mt = 0; mt < 2; ++mt) {
#pragma unroll
        for (int nt = 0; nt < NTN; ++nt) {
            const int n  = n0 + wn * WN + nt * 8 + 2 * (lane & 3);
            const int mlo = m0 + wm * 32 + mt * 16 + (lane >> 2);
            float v0 = acc[mt][nt][0], v1 = acc[mt][nt][1];
            float v2 = acc[mt][nt][2], v3 = acc[mt][nt][3];
            float b0 = bias[n], b1 = bias[n + 1];
            if (MODE == M_PLAIN) {
                *(float2*)(p.C + (long long)mlo * p.N + n)       = make_float2(v0 + b0, v1 + b1);
                *(float2*)(p.C + (long long)(mlo + 8) * p.N + n) = make_float2(v2 + b0, v3 + b1);
            } else if (MODE == M_RELU) {
                float o0 = v0 + b0, o1 = v1 + b1, o2 = v2 + b0, o3 = v3 + b1;
                o0 = o0 > 0.f ? o0 : 0.f; o1 = o1 > 0.f ? o1 : 0.f;
                o2 = o2 > 0.f ? o2 : 0.f; o3 = o3 > 0.f ? o3 : 0.f;
                *(__nv_bfloat162*)(p.Cb + (long long)mlo * p.N + n)       = __floats2bfloat162_rn(o0, o1);
                *(__nv_bfloat162*)(p.Cb + (long long)(mlo + 8) * p.N + n) = __floats2bfloat162_rn(o2, o3);
            }
        }
    }
}

// ======================= small GEMM: BM=64, BN=64, 128 threads, 4 CTAs/SM =======================
// Few-wave small-N GEMMs: QKV, Wo, W2.
#define SSMEM 49152

template<int MODE>
__global__ __launch_bounds__(128, 4) void small_k(GP p) {
    constexpr int ABYTES = 64 * 128;
    constexpr int STG    = 2 * ABYTES;

    extern __shared__ char sm[];
    const u32 sb = sm32(sm);
    const int t = threadIdx.x, lane = t & 31, warp = t >> 5;
    const int wm = warp >> 1, wn = warp & 1;
    const int n0 = blockIdx.x * 64, m0 = blockIdx.y * 64, z = blockIdx.z;

    const bf16* A = p.A;
    const bf16* B; const float* bias;
    if (MODE == M_QKV) {
        B    = (z == 0) ? p.B : (z == 1 ? p.B1 : p.B2);
        bias = (z == 0) ? p.bias : (z == 1 ? p.bias1 : p.bias2);
    } else { B = p.B; bias = p.bias; }

    const int ntile = p.K >> 6;

    auto fill = [&](int it) {
        u32 ab = sb + (it % 3) * STG;
        u32 bb = ab + ABYTES;
        int k0 = it << 6;
        const bf16* Ag = A + (long long)m0 * p.K + k0;
        const bf16* Bg = B + (long long)n0 * p.K + k0;
#pragma unroll
        for (int i = 0; i < 4; ++i) {
            int idx = t + i * 128;
            int r = idx >> 3, c = idx & 7;
            cp_async16(ab + r * 128 + ((c ^ (r & 7)) << 4), Ag + (long long)r * p.K + c * 8);
        }
#pragma unroll
        for (int i = 0; i < 4; ++i) {
            int idx = t + i * 128;
            int r = idx >> 3, c = idx & 7;
            cp_async16(bb + r * 128 + ((c ^ (r & 7)) << 4), Bg + (long long)r * p.K + c * 8);
        }
        CP_COMMIT();
    };

    float acc[2][4][4];
#pragma unroll
    for (int i = 0; i < 2; ++i)
#pragma unroll
        for (int j = 0; j < 4; ++j)
#pragma unroll
            for (int c = 0; c < 4; ++c) acc[i][j][c] = 0.f;

    fill(0);
    if (1 < ntile) fill(1);

    for (int it = 0; it < ntile; ++it) {
        if (it + 1 < ntile) { CP_WAIT(1); } else { CP_WAIT(0); }
        __syncthreads();
        if (it + 2 < ntile) fill(it + 2);

        u32 ab = sb + (it % 3) * STG;
        u32 bb = ab + ABYTES;
#pragma unroll
        for (int ks = 0; ks < 4; ++ks) {
            const int cc = ks * 2 + (lane >> 4);
            u32 a[2][4];
#pragma unroll
            for (int mt = 0; mt < 2; ++mt) {
                int mr = wm * 32 + mt * 16 + (lane & 7) + ((lane >> 3) & 1) * 8;
                LDSM4(a[mt], ab + mr * 128 + ((cc ^ (mr & 7)) << 4));
            }
#pragma unroll
            for (int nb = 0; nb < 2; ++nb) {
                int nr = wn * 32 + nb * 16 + (lane & 7) + ((lane >> 3) & 1) * 8;
                u32 b[4];
                LDSM4(b, bb + nr * 128 + ((cc ^ (nr & 7)) << 4));
#pragma unroll
                for (int mt = 0; mt < 2; ++mt) {
                    mma16816(acc[mt][2 * nb + 0], a[mt], b[0], b[2]);
                    mma16816(acc[mt][2 * nb + 1], a[mt], b[1], b[3]);
                }
            }
        }
    }

#pragma unroll
    for (int mt = 0; mt < 2; ++mt) {
#pragma unroll
        for (int nt = 0; nt < 4; ++nt) {
            const int n  = n0 + wn * 32 + nt * 8 + 2 * (lane & 3);
            const int mlo = m0 + wm * 32 + mt * 16 + (lane >> 2);
            float v0 = acc[mt][nt][0], v1 = acc[mt][nt][1];
            float v2 = acc[mt][nt][2], v3 = acc[mt][nt][3];
            float b0 = bias[n], b1 = bias[n + 1];
            if (MODE == M_RESID) {
                long long i0 = (long long)mlo * p.N + n;
                long long i1 = (long long)(mlo + 8) * p.N + n;
                float2 r0 = *(float2*)(p.resid + i0), r1 = *(float2*)(p.resid + i1);
                *(float2*)(p.C + i0) = make_float2(r0.x + v0 + b0, r0.y + v1 + b1);
                *(float2*)(p.C + i1) = make_float2(r1.x + v2 + b0, r1.y + v3 + b1);
            } else if (MODE == M_QKV) {
                float o0 = v0 + b0, o1 = v1 + b1, o2 = v2 + b0, o3 = v3 + b1;
                const long long TSZ = (long long)BB * SQ * DIM;
                int hh = n >> 6, dk = n & 63;
#pragma unroll
                for (int half = 0; half < 2; ++half) {
                    int m = mlo + half * 8;
                    int b = m >> 10, s2 = m & (SQ - 1);
                    float e0 = half ? o2 : o0, e1 = half ? o3 : o1;
                    if (z < 2) {
                        *(__nv_bfloat162*)(p.Cb + z * TSZ + (((long long)(b * NH + hh)) * SQ + s2) * DKH + dk)
                            = __floats2bfloat162_rn(e0, e1);
                    } else {
                        bf16* base = p.Cb + 2 * TSZ + ((long long)(b * NH + hh)) * DKH * SQ + s2;
                        base[(long long)dk * SQ]       = __float2bfloat16_rn(e0);
                        base[(long long)(dk + 1) * SQ] = __float2bfloat16_rn(e1);
                    }
                }
            }
        }
    }
}

// ======================= fused flash attention (BM=128, proven) =======================
#define FA_QBYTES  16384
#define FA_KBYTES  16384
#define FA_VBYTES  16384
#define FA_STG     (FA_KBYTES + FA_VBYTES + 512)
#define FA_SMEM    (FA_QBYTES + 2 * FA_STG)

__global__ __launch_bounds__(256) void flash_k(const bf16* __restrict__ qg,
                                               const bf16* __restrict__ kg,
                                               const bf16* __restrict__ vg,
                                               const float* __restrict__ rbias,
                                               bf16* __restrict__ at) {
    extern __shared__ char sm[];
    const u32 sb = sm32(sm);
    const int t = threadIdx.x, lane = t & 31, warp = t >> 5;
    const int qb = blockIdx.x, z = blockIdx.y;
    const int b = z >> 3, h = z & 7;

    const bf16* Qg = qg + ((long long)z * SQ + qb * 128) * DKH;
    const bf16* Kg = kg + (long long)z * SQ * DKH;
    const bf16* Vg = vg + (long long)z * DKH * SQ;
    const float* rbg = rbias + (long long)z * SQ;

    const int nkb = qb + 1;

#pragma unroll
    for (int i = 0; i < 4; ++i) {
        int idx = t + i * 256;
        int r = idx >> 3, c = idx & 7;
        cp_async16(sb + r * 128 + ((c ^ (r & 7)) << 4), Qg + (long long)r * DKH + c * 8);
    }
    auto fillKV = [&](int kb) {
        u32 kbse = sb + FA_QBYTES + (kb & 1) * FA_STG;
        u32 vbse = kbse + FA_KBYTES;
        u32 rbse = vbse + FA_VBYTES;
        const bf16* Kt = Kg + (long long)kb * 128 * DKH;
        const bf16* Vt = Vg + kb * 128;
#pragma unroll
        for (int i = 0; i < 4; ++i) {
            int idx = t + i * 256;
            int r = idx >> 3, c = idx & 7;
            cp_async16(kbse + r * 128 + ((c ^ (r & 7)) << 4), Kt + (long long)r * DKH + c * 8);
        }
#pragma unroll
        for (int i = 0; i < 4; ++i) {
            int idx = t + i * 256;
            int r = idx >> 4, c = idx & 15;
            cp_async16(vbse + r * 256 + ((c ^ (r & 7)) << 4), Vt + (long long)r * SQ + c * 8);
        }
        if (t < 32) cp_async16(rbse + t * 16, rbg + kb * 128 + t * 4);
        CP_COMMIT();
    };
    fillKV(0);

    float o[8][4];
#pragma unroll
    for (int i = 0; i < 8; ++i)
#pragma unroll
        for (int c = 0; c < 4; ++c) o[i][c] = 0.f;
    float m0 = -1e30f, m1 = -1e30f, l0 = 0.f, l1 = 0.f;

    u32 aq[4][4];
    bool qloaded = false;

    for (int kb = 0; kb < nkb; ++kb) {
        CP_WAIT(0);
        __syncthreads();
        if (kb + 1 < nkb) fillKV(kb + 1);

        if (!qloaded) {
#pragma unroll
            for (int ks = 0; ks < 4; ++ks) {
                int mr = warp * 16 + (lane & 7) + ((lane >> 3) & 1) * 8;
                int cc = ks * 2 + (lane >> 4);
                LDSM4(aq[ks], sb + mr * 128 + ((cc ^ (mr & 7)) << 4));
            }
            qloaded = true;
        }

        u32 kbse = sb + FA_QBYTES + (kb & 1) * FA_STG;
        u32 vbse = kbse + FA_KBYTES;
        float* rbs = (float*)(sm + (kbse - sb) + FA_KBYTES + FA_VBYTES);

        float s[16][4];
#pragma unroll
        for (int i = 0; i < 16; ++i)
#pragma unroll
            for (int c = 0; c < 4; ++c) s[i][c] = 0.f;
#pragma unroll
        for (int ks = 0; ks < 4; ++ks) {
            const int cc = ks * 2 + (lane >> 4);
#pragma unroll
            for (int np = 0; np < 8; ++np) {
                int nr = np * 16 + (lane & 7) + ((lane >> 3) & 1) * 8;
                u32 bfr[4];
                LDSM4(bfr, kbse + nr * 128 + ((cc ^ (nr & 7)) << 4));
                mma16816(s[2 * np + 0], aq[ks], bfr[0], bfr[2]);
                mma16816(s[2 * np + 1], aq[ks], bfr[1], bfr[3]);
            }
        }

        const int colq = 2 * (lane & 3);
        const int r0 = warp * 16 + (lane >> 2), r1 = r0 + 8;
#pragma unroll
        for (int nt = 0; nt < 16; ++nt) {
            float2 rb2 = *(float2*)(rbs + nt * 8 + colq);
            s[nt][0] = s[nt][0] * 0.125f + rb2.x;
            s[nt][1] = s[nt][1] * 0.125f + rb2.y;
            s[nt][2] = s[nt][2] * 0.125f + rb2.x;
            s[nt][3] = s[nt][3] * 0.125f + rb2.y;
        }
        if (kb == qb) {
#pragma unroll
            for (int nt = 0; nt < 16; ++nt) {
                int c0 = nt * 8 + colq;
                if (c0 > r0)     s[nt][0] = -1e30f;
                if (c0 + 1 > r0) s[nt][1] = -1e30f;
                if (c0 > r1)     s[nt][2] = -1e30f;
                if (c0 + 1 > r1) s[nt][3] = -1e30f;
            }
        }

        float mx0 = -1e30f, mx1 = -1e30f;
#pragma unroll
        for (int nt = 0; nt < 16; ++nt) {
            mx0 = fmaxf(mx0, fmaxf(s[nt][0], s[nt][1]));
            mx1 = fmaxf(mx1, fmaxf(s[nt][2], s[nt][3]));
        }
        mx0 = fmaxf(mx0, __shfl_xor_sync(0xffffffffu, mx0, 1));
        mx0 = fmaxf(mx0, __shfl_xor_sync(0xffffffffu, mx0, 2));
        mx1 = fmaxf(mx1, __shfl_xor_sync(0xffffffffu, mx1, 1));
        mx1 = fmaxf(mx1, __shfl_xor_sync(0xffffffffu, mx1, 2));
        float M0 = fmaxf(m0, mx0), M1 = fmaxf(m1, mx1);
        float a0 = expf(m0 - M0), a1 = expf(m1 - M1);
        float sum0 = 0.f, sum1 = 0.f;
#pragma unroll
        for (int nt = 0; nt < 16; ++nt) {
            s[nt][0] = expf(s[nt][0] - M0); sum0 += s[nt][0];
            s[nt][1] = expf(s[nt][1] - M0); sum0 += s[nt][1];
            s[nt][2] = expf(s[nt][2] - M1); sum1 += s[nt][2];
            s[nt][3] = expf(s[nt][3] - M1); sum1 += s[nt][3];
        }
        sum0 += __shfl_xor_sync(0xffffffffu, sum0, 1);
        sum0 += __shfl_xor_sync(0xffffffffu, sum0, 2);
        sum1 += __shfl_xor_sync(0xffffffffu, sum1, 1);
        sum1 += __shfl_xor_sync(0xffffffffu, sum1, 2);
        l0 = l0 * a0 + sum0;  l1 = l1 * a1 + sum1;
        m0 = M0;  m1 = M1;
#pragma unroll
        for (int i = 0; i < 8; ++i) {
            o[i][0] *= a0; o[i][1] *= a0; o[i][2] *= a1; o[i][3] *= a1;
        }

#pragma unroll
        for (int kv = 0; kv < 8; ++kv) {
            u32 pa[4];
            pa[0] = pack_bf(s[2 * kv][0],     s[2 * kv][1]);
            pa[1] = pack_bf(s[2 * kv][2],     s[2 * kv][3]);
            pa[2] = pack_bf(s[2 * kv + 1][0], s[2 * kv + 1][1]);
            pa[3] = pack_bf(s[2 * kv + 1][2], s[2 * kv + 1][3]);
            const int cc = kv * 2 + (lane >> 4);
#pragma unroll
            for (int nd = 0; nd < 4; ++nd) {
                int nr = nd * 16 + (lane & 7) + ((lane >> 3) & 1) * 8;
                u32 bfr[4];
                LDSM4(bfr, vbse + nr * 256 + ((cc ^ (nr & 7)) << 4));
                mma16816(o[2 * nd + 0], pa, bfr[0], bfr[2]);
                mma16816(o[2 * nd + 1], pa, bfr[1], bfr[3]);
            }
        }
        __syncthreads();
    }

    float inv0 = 1.f / l0, inv1 = 1.f / l1;
    const int r0 = qb * 128 + warp * 16 + (lane >> 2);
#pragma unroll
    for (int nd = 0; nd < 8; ++nd) {
        int n = h * DKH + nd * 8 + 2 * (lane & 3);
        __nv_bfloat162 v0 = __floats2bfloat162_rn(o[nd][0] * inv0, o[nd][1] * inv0);
        __nv_bfloat162 v1 = __floats2bfloat162_rn(o[nd][2] * inv1, o[nd][3] * inv1);
        *(__nv_bfloat162*)(at + ((long long)(b * SQ) + r0) * DIM + n)     = v0;
        *(__nv_bfloat162*)(at + ((long long)(b * SQ) + r0 + 8) * DIM + n) = v1;
    }
}

// ---------------- merged weight f32 -> bf16 conversion ----------------
struct CvtAll { const float* s[7]; bf16* d[7]; int cum[8]; };
__global__ __launch_bounds__(256) void cvtall_k(CvtAll j) {
    int g = blockIdx.x * 256 + threadIdx.x;
    if (g >= j.cum[7]) return;
    int seg = 0;
#pragma unroll
    for (int i = 1; i < 7; ++i) seg += (g >= j.cum[i]);
    int local = g - j.cum[seg];
    float4 v = ((const float4*)j.s[seg])[local];
    __nv_bfloat162* d2 = (__nv_bfloat162*)j.d[seg] + (long long)local * 2;
    d2[0] = __floats2bfloat162_rn(v.x, v.y);
    d2[1] = __floats2bfloat162_rn(v.z, v.w);
}

// ---------------- shared LN math (shuffle reductions) ----------------
__device__ __forceinline__ void ln_write(float v0, float v1, const float* ga,
                                         const float* be, bf16* yr, int t,
                                         float* wred) {
    int lane = t & 31, w = t >> 5;
    float s = v0 + v1;
#pragma unroll
    for (int o = 16; o > 0; o >>= 1) s += __shfl_xor_sync(0xffffffffu, s, o);
    if (lane == 0) wred[w] = s;
    __syncthreads();
    if (w == 0) {
        float a = (lane < 8) ? wred[lane] : 0.f;
#pragma unroll
        for (int o = 4; o > 0; o >>= 1) a += __shfl_xor_sync(0xffffffffu, a, o);
        if (lane == 0) wred[8] = a;
    }
    __syncthreads();
    float mean = wred[8] * (1.f / (float)DIM);
    float d0 = v0 - mean, d1 = v1 - mean;
    float q = d0 * d0 + d1 * d1;
#pragma unroll
    for (int o = 16; o > 0; o >>= 1) q += __shfl_xor_sync(0xffffffffu, q, o);
    if (lane == 0) wred[w] = q;
    __syncthreads();
    if (w == 0) {
        float a = (lane < 8) ? wred[lane] : 0.f;
#pragma unroll
        for (int o = 4; o > 0; o >>= 1) a += __shfl_xor_sync(0xffffffffu, a, o);
        if (lane == 0) wred[8] = a;
    }
    __syncthreads();
    float stdv = sqrtf(wred[8] / (float)(DIM - 1));
    float inv  = 1.f / (stdv + 1e-6f);
    yr[t]       = __float2bfloat16_rn(ga[t] * d0 * inv + be[t]);
    yr[t + 256] = __float2bfloat16_rn(ga[t + 256] * d1 * inv + be[t + 256]);
}

__global__ void ln_k(const float* x, const float* ga, const float* be, bf16* y) {
    __shared__ float wred[9];
    int row = blockIdx.x, t = threadIdx.x;
    const float* xr = x + (long long)row * DIM;
    float v0 = xr[t], v1 = xr[t + 256];
    ln_write(v0, v1, ga, be, y + (long long)row * DIM, t, wred);
}

// ---------------- embedding + PE, fused with layer-0 LN ----------------
__global__ void embed_k(const int* inp, const float* emb,
                        const float* ga, const float* be,
                        float* x, bf16* h) {
    __shared__ float wred[9];
    int row = blockIdx.x, t = threadIdx.x;
    int s   = row & (SQ - 1);
    int tok = inp[row];
    const float* e = emb + (long long)tok * DIM;
    const float ln10k_over_d = 9.210340371976184f / (float)DIM;
    float v[2];
#pragma unroll
    for (int i = 0; i < 2; ++i) {
        int d = t + i * 256;
        int   i2  = d & ~1;
        float dv  = expf(-(float)i2 * ln10k_over_d);
        float arg = (float)s * dv;
        float pe  = (d & 1) ? cosf(arg) : sinf(arg);
        v[i] = e[d] * 22.62741699796952f + pe;
        x[(long long)row * DIM + d] = v[i];
    }
    ln_write(v[0], v[1], ga, be, h + (long long)row * DIM, t, wred);
}

// ---------------- relative bias: r[b,h,k] = scale * dot(q[b,h,k], pe[h,k]) ----
__global__ void relbias_k(const bf16* q, const float* rel, float* r) {
    int idx  = blockIdx.x * 8 + (threadIdx.x >> 5);
    int lane = threadIdx.x & 31;
    int k = idx & (SQ - 1);
    int h = (idx >> 10) & (NH - 1);
    const bf16*  qp = q   + (long long)idx * DKH;
    const float* pp = rel + ((long long)h * MAXS + k) * DKH;
    float d = __bfloat162float(qp[lane]) * pp[lane]
            + __bfloat162float(qp[lane + 32]) * pp[lane + 32];
    for (int o = 16; o > 0; o >>= 1) d += __shfl_xor_sync(0xffffffffu, d, o);
    if (lane == 0) r[idx] = d * 0.125f;
}

// ---------------- log_softmax: smem row cache, 1024 threads, shuffle reductions ----
#define LS_SMEM (NV * 4)
__global__ __launch_bounds__(1024) void logsoftmax_k(float* out) {
    extern __shared__ float row[];
    __shared__ float wred[33];
    float* r = out + (long long)blockIdx.x * NV;
    const int t = threadIdx.x, lane = t & 31, w = t >> 5;

    float mx = -1e30f;
    for (int k = t * 4; k < NV; k += 4096) {
        float4 v = *(const float4*)(r + k);
        *(float4*)(row + k) = v;
        mx = fmaxf(mx, fmaxf(fmaxf(v.x, v.y), fmaxf(v.z, v.w)));
    }
#pragma unroll
    for (int o = 16; o > 0; o >>= 1) mx = fmaxf(mx, __shfl_xor_sync(0xffffffffu, mx, o));
    if (lane == 0) wred[w] = mx;
    __syncthreads();
    if (w == 0) {
        float a = wred[lane];
#pragma unroll
        for (int o = 16; o > 0; o >>= 1) a = fmaxf(a, __shfl_xor_sync(0xffffffffu, a, o));
        if (lane == 0) wred[32] = a;
    }
    __syncthreads();
    mx = wred[32];

    float sum = 0.f;
    for (int k = t * 4; k < NV; k += 4096) {
        float4 v = *(const float4*)(row + k);
        sum += expf(v.x - mx) + expf(v.y - mx) + expf(v.z - mx) + expf(v.w - mx);
    }
#pragma unroll
    for (int o = 16; o > 0; o >>= 1) sum += __shfl_xor_sync(0xffffffffu, sum, o);
    if (lane == 0) wred[w] = sum;
    __syncthreads();
    if (w == 0) {
        float a = wred[lane];
#pragma unroll
        for (int o = 16; o > 0; o >>= 1) a += __shfl_xor_sync(0xffffffffu, a, o);
        if (lane == 0) wred[32] = a;
    }
    __syncthreads();
    const float lse = mx + logf(wred[32]);

    for (int k = t * 4; k < NV; k += 4096) {
        float4 v = *(const float4*)(row + k);
        v.x -= lse; v.y -= lse; v.z -= lse; v.w -= lse;
        *(float4*)(r + k) = v;
    }
}

// ---------------- host driver ----------------
static inline GP mkgp(const bf16* A, const bf16* B, const float* bias, int N, int K) {
    GP p; p.A = A; p.B = B; p.B1 = nullptr; p.B2 = nullptr;
    p.bias = bias; p.bias1 = nullptr; p.bias2 = nullptr;
    p.resid = nullptr; p.C = nullptr; p.Cb = nullptr;
    p.N = N; p.K = K;
    return p;
}

extern "C" void kernel_launch(void* const* d_in, const int* in_sizes, int n_in,
                              void* d_out, int out_size) {
    const int*   inp   = (const int*)  d_in[0];
    const float* emb   = (const float*)d_in[2];
    const float* Wq    = (const float*)d_in[3];
    const float* bq    = (const float*)d_in[4];
    const float* Wk    = (const float*)d_in[5];
    const float* bk    = (const float*)d_in[6];
    const float* Wv    = (const float*)d_in[7];
    const float* bv    = (const float*)d_in[8];
    const float* Wo    = (const float*)d_in[9];
    const float* bo    = (const float*)d_in[10];
    const float* rel   = (const float*)d_in[11];
    const float* ln1a  = (const float*)d_in[12];
    const float* ln1b  = (const float*)d_in[13];
    const float* ln2a  = (const float*)d_in[14];
    const float* ln2b  = (const float*)d_in[15];
    const float* W1    = (const float*)d_in[16];
    const float* b1    = (const float*)d_in[17];
    const float* W2    = (const float*)d_in[18];
    const float* b2    = (const float*)d_in[19];
    const float* lnfa  = (const float*)d_in[20];
    const float* lnfb  = (const float*)d_in[21];
    const float* Wg    = (const float*)d_in[22];
    const float* bg    = (const float*)d_in[23];
    float* out = (float*)d_out;

    float *x, *rb;
    bf16 *h, *qkvb, *at, *ff, *wb;
    cudaGetSymbolAddress((void**)&x,    g_x);
    cudaGetSymbolAddress((void**)&h,    g_h);
    cudaGetSymbolAddress((void**)&qkvb, g_qkvb);
    cudaGetSymbolAddress((void**)&rb,   g_rb);
    cudaGetSymbolAddress((void**)&at,   g_at);
    cudaGetSymbolAddress((void**)&ff,   g_ff);
    cudaGetSymbolAddress((void**)&wb,   g_wb);

    const int Mtok = BB * SQ;                     // 2048
    const long long TSZ = (long long)Mtok * DIM;  // 1,048,576
    bf16* q  = qkvb;
    bf16* k_ = qkvb + TSZ;
    bf16* vt = qkvb + 2 * TSZ;

    cudaFuncSetAttribute(bmma_k<M_PLAIN, 128>, cudaFuncAttributeMaxDynamicSharedMemorySize, GSMEM(128));
    cudaFuncSetAttribute(bmma_k<M_RELU,  128>, cudaFuncAttributeMaxDynamicSharedMemorySize, GSMEM(128));
    cudaFuncSetAttribute(small_k<M_QKV>,   cudaFuncAttributeMaxDynamicSharedMemorySize, SSMEM);
    cudaFuncSetAttribute(small_k<M_RESID>, cudaFuncAttributeMaxDynamicSharedMemorySize, SSMEM);
    cudaFuncSetAttribute(flash_k,      cudaFuncAttributeMaxDynamicSharedMemorySize, FA_SMEM);
    cudaFuncSetAttribute(logsoftmax_k, cudaFuncAttributeMaxDynamicSharedMemorySize, LS_SMEM);

    // ---- all weights -> bf16 in one launch ----
    {
        const int n1 = NL * DIM * DIM / 4;
        const int n2 = NL * DFF * DIM / 4;
        const int ng = NV * DIM / 4;
        CvtAll j;
        j.s[0] = Wq; j.s[1] = Wk; j.s[2] = Wv; j.s[3] = Wo; j.s[4] = W1; j.s[5] = W2; j.s[6] = Wg;
        j.d[0] = wb + OFF_WQ; j.d[1] = wb + OFF_WK; j.d[2] = wb + OFF_WV; j.d[3] = wb + OFF_WO;
        j.d[4] = wb + OFF_W1; j.d[5] = wb + OFF_W2; j.d[6] = wb + OFF_WG;
        j.cum[0] = 0;
        j.cum[1] = n1; j.cum[2] = 2 * n1; j.cum[3] = 3 * n1; j.cum[4] = 4 * n1;
        j.cum[5] = 4 * n1 + n2; j.cum[6] = 4 * n1 + 2 * n2; j.cum[7] = 4 * n1 + 2 * n2 + ng;
        cvtall_k<<<(j.cum[7] + 255) / 256, 256>>>(j);
    }

    // embedding + layer-0 LN fused
    embed_k<<<Mtok, 256>>>(inp, emb, ln1a, ln1b, x, h);

    for (int l = 0; l < NL; ++l) {
        const long long wOff = (long long)l * DIM * DIM;
        const long long fOff = (long long)l * DFF * DIM;

        if (l > 0)
            ln_k<<<Mtok, 256>>>(x, ln1a + l * DIM, ln1b + l * DIM, h);

        // fused QKV (small_k: 768 CTAs, 4 CTAs/SM)
        {
            GP p = mkgp(h, wb + OFF_WQ + wOff, bq + l * DIM, DIM, DIM);
            p.B1 = wb + OFF_WK + wOff;  p.B2 = wb + OFF_WV + wOff;
            p.bias1 = bk + l * DIM;     p.bias2 = bv + l * DIM;
            p.Cb = qkvb;
            small_k<M_QKV><<<dim3(DIM / 64, Mtok / 64, 3), 128, SSMEM>>>(p);
        }

        relbias_k<<<BB * NH * SQ / 8, 256>>>(q, rel + (long long)l * NH * MAXS * DKH, rb);

        flash_k<<<dim3(SQ / 128, BB * NH), 256, FA_SMEM>>>(q, k_, vt, rb, at);

        // x = x + attn @ Wo^T + bo (small_k)
        {
            GP p = mkgp(at, wb + OFF_WO + wOff, bo + l * DIM, DIM, DIM);
            p.resid = x; p.C = x;
            small_k<M_RESID><<<dim3(DIM / 64, Mtok / 64, 1), 128, SSMEM>>>(p);
        }

        ln_k<<<Mtok, 256>>>(x, ln2a + l * DIM, ln2b + l * DIM, h);

        // ffn = relu(h @ W1^T + b1) -> bf16 (bmma_k BN=128)
        {
            GP p = mkgp(h, wb + OFF_W1 + fOff, b1 + l * DFF, DFF, DIM);
            p.Cb = ff;
            bmma_k<M_RELU, 128><<<dim3(DFF / 128, Mtok / 128, 1), 256, GSMEM(128)>>>(p);
        }
        // x = x + ffn @ W2^T + b2 (small_k)
        {
            GP p = mkgp(ff, wb + OFF_W2 + fOff, b2 + l * DIM, DIM, DFF);
            p.resid = x; p.C = x;
            small_k<M_RESID><<<dim3(DIM / 64, Mtok / 64, 1), 128, SSMEM>>>(p);
        }
    }

    ln_k<<<Mtok, 256>>>(x, lnfa, lnfb, h);

    // logits = h @ Wg^T + bg -> d_out (bmma_k BN=128)
    {
        GP p = mkgp(h, wb + OFF_WG, bg, NV, DIM);
        p.C = out;
        bmma_k<M_PLAIN, 128><<<dim3(NV / 128, Mtok / 128, 1), 256, GSMEM(128)>>>(p);
    }

    logsoftmax_k<<<Mtok, 1024, LS_SMEM>>>(out);
}